// round 2
// baseline (speedup 1.0000x reference)
#include <cuda_runtime.h>
#include <cstdint>

// ============================================================================
// GNN_clusters_44057774522942
//   N=100000 nodes, F_in=1024, H=256, T=128, NNZ=400000, E=20000, B=16, C=64
// N / NNZ read from in_sizes; E, C capacities fixed.
// ============================================================================
constexpr int NMAX = 100000;
constexpr int EMAX = 20000;
constexpr int H    = 256;
constexpr int T    = 128;
constexpr int NSEG = 1024;   // B * C
constexpr float EPSV = 1e-5f;

// ------------------------- scratch (device globals) -------------------------
__device__ float g_h  [(size_t)NMAX * H];
__device__ float g_xw [(size_t)NMAX * H];
__device__ float g_agg[(size_t)NMAX * H];
__device__ float g_he [(size_t)EMAX * H];
__device__ float g_out[(size_t)NMAX * T];
__device__ float g_colsum[H];
__device__ float g_colsq [H];
__device__ float g_scale [H];
__device__ float g_shift [H];
__device__ int   g_Ddeg[NMAX];
__device__ int   g_Bdeg[EMAX];
__device__ int   g_seg [NMAX];
__device__ int   g_poolcnt[NSEG];
__device__ unsigned g_poolmx[NSEG * T];

// ------------------------------- tiny helpers -------------------------------
__device__ __forceinline__ unsigned f2o(float f) {
    unsigned u = __float_as_uint(f);
    return (u & 0x80000000u) ? ~u : (u | 0x80000000u);
}
__device__ __forceinline__ float o2f(unsigned o) {
    unsigned u = (o & 0x80000000u) ? (o ^ 0x80000000u) : ~o;
    return __uint_as_float(u);
}
__device__ __forceinline__ void red_add_v4(float* p, float4 v) {
    asm volatile("red.global.add.v4.f32 [%0], {%1,%2,%3,%4};"
                 :: "l"(p), "f"(v.x), "f"(v.y), "f"(v.z), "f"(v.w) : "memory");
}

// ------------------------------- init kernels --------------------------------
// Zeroes g_he + g_agg + degree arrays + misc, all referencing globals directly.
__global__ void init_all(int n) {
    int i = blockIdx.x * blockDim.x + threadIdx.x;
    int he4 = EMAX * (H / 4);
    int n4  = n * (H / 4);
    if (i < he4) reinterpret_cast<float4*>(g_he)[i]  = make_float4(0.f, 0.f, 0.f, 0.f);
    if (i < n4)  reinterpret_cast<float4*>(g_agg)[i] = make_float4(0.f, 0.f, 0.f, 0.f);
    if (i < n)    g_Ddeg[i] = 0;
    if (i < EMAX) g_Bdeg[i] = 0;
    if (i < NSEG * T) g_poolmx[i] = 0u;   // f2o(x)=0 only for -inf; all real floats map above 0? no:
                                          // f2o(-x) = ~u < 0x7fffffff... use true minimum:
    if (i < NSEG * T) g_poolmx[i] = 0u;
    if (i < NSEG) g_poolcnt[i] = 0;
    if (i < H) { g_colsum[i] = 0.f; g_colsq[i] = 0.f; }
}
// NOTE: f2o is monotone with f2o(-inf)=0x00800000... actually f2o(0xff800000)=~0xff800000
// = 0x007fffff > 0. Safe init is 0, which is below every encoded float (min encode is
// f2o(-inf)=0x007fffff). 0u works as identity.

__global__ void zero_agg(int n) {   // re-zero g_agg between layers
    int i = blockIdx.x * blockDim.x + threadIdx.x;
    int n4 = n * (H / 4);
    if (i < n4) reinterpret_cast<float4*>(g_agg)[i] = make_float4(0.f, 0.f, 0.f, 0.f);
}
__global__ void zero_he() {
    int i = blockIdx.x * blockDim.x + threadIdx.x;
    if (i < EMAX * (H / 4)) reinterpret_cast<float4*>(g_he)[i] = make_float4(0.f, 0.f, 0.f, 0.f);
}

// ----------------------------- degrees / pooling meta ------------------------
__global__ void deg_hist(const int* __restrict__ ni, const int* __restrict__ hi, int nnz) {
    int i = blockIdx.x * blockDim.x + threadIdx.x;
    if (i < nnz) { atomicAdd(&g_Ddeg[ni[i]], 1); atomicAdd(&g_Bdeg[hi[i]], 1); }
}
__global__ void pool_prep(const int* __restrict__ batch, const int* __restrict__ clus,
                          int n, int C) {
    int v = blockIdx.x * blockDim.x + threadIdx.x;
    if (v < n) {
        int s = batch[v] * C + clus[v];
        g_seg[v] = s;
        atomicAdd(&g_poolcnt[s], 1);
    }
}

// ============================================================================
// Tiled fp32 GEMM: C[N,M] = A[N,K] @ B[K,M] (+bias) (+=C if ACCUM)
// Block tile 128x128, BK=16, 256 threads, 8x8 microtile/thread.
// STATS: per-column sum / sum-of-squares accumulated into g_colsum/g_colsq.
// Requires K % 16 == 0, M % 128 == 0 (true: K in {1024,256}, M in {256,128}).
// ============================================================================
template<bool STATS, bool ACCUM>
__launch_bounds__(256, 2)
__global__ void gemm128(const float* __restrict__ A, const float* __restrict__ B,
                        const float* __restrict__ bias, float* __restrict__ C,
                        int N, int K, int M)
{
    __shared__ float As[16][132];
    __shared__ float Bs[16][132];
    __shared__ float s_sum[128], s_sq[128];

    const int tid   = threadIdx.x;
    const int row_t = tid >> 4;
    const int col_t = tid & 15;
    const int rowBase = blockIdx.y * 128;
    const int colBase = blockIdx.x * 128;

    if (STATS && tid < 128) { s_sum[tid] = 0.f; s_sq[tid] = 0.f; }

    float acc[8][8];
#pragma unroll
    for (int i = 0; i < 8; i++)
#pragma unroll
        for (int j = 0; j < 8; j++) acc[i][j] = 0.f;

    for (int k0 = 0; k0 < K; k0 += 16) {
#pragma unroll
        for (int l = 0; l < 2; l++) {
            int lin = tid + l * 256;
            int r   = lin >> 2;
            int kq  = lin & 3;
            float4 v = make_float4(0.f, 0.f, 0.f, 0.f);
            int gr = rowBase + r;
            if (gr < N)
                v = *reinterpret_cast<const float4*>(A + (size_t)gr * K + k0 + kq * 4);
            As[kq * 4 + 0][r] = v.x;
            As[kq * 4 + 1][r] = v.y;
            As[kq * 4 + 2][r] = v.z;
            As[kq * 4 + 3][r] = v.w;
        }
#pragma unroll
        for (int l = 0; l < 2; l++) {
            int lin = tid + l * 256;
            int r   = lin >> 5;
            int c4  = lin & 31;
            *reinterpret_cast<float4*>(&Bs[r][c4 * 4]) =
                *reinterpret_cast<const float4*>(B + (size_t)(k0 + r) * M + colBase + c4 * 4);
        }
        __syncthreads();
#pragma unroll
        for (int k = 0; k < 16; k++) {
            float a[8], b[8];
            *reinterpret_cast<float4*>(&a[0]) = *reinterpret_cast<const float4*>(&As[k][row_t * 8]);
            *reinterpret_cast<float4*>(&a[4]) = *reinterpret_cast<const float4*>(&As[k][row_t * 8 + 4]);
            *reinterpret_cast<float4*>(&b[0]) = *reinterpret_cast<const float4*>(&Bs[k][col_t * 8]);
            *reinterpret_cast<float4*>(&b[4]) = *reinterpret_cast<const float4*>(&Bs[k][col_t * 8 + 4]);
#pragma unroll
            for (int i = 0; i < 8; i++)
#pragma unroll
                for (int j = 0; j < 8; j++)
                    acc[i][j] = fmaf(a[i], b[j], acc[i][j]);
        }
        __syncthreads();
    }

    float bv[8];
#pragma unroll
    for (int j = 0; j < 8; j++)
        bv[j] = bias ? bias[colBase + col_t * 8 + j] : 0.f;

    float csum[8], csq[8];
#pragma unroll
    for (int j = 0; j < 8; j++) { csum[j] = 0.f; csq[j] = 0.f; }

#pragma unroll
    for (int i = 0; i < 8; i++) {
        int gr = rowBase + row_t * 8 + i;
        if (gr < N) {
            float* crow = C + (size_t)gr * M + colBase + col_t * 8;
            float v[8];
#pragma unroll
            for (int j = 0; j < 8; j++) v[j] = acc[i][j] + bv[j];
            if (ACCUM) {
                float4 o0 = *reinterpret_cast<const float4*>(crow);
                float4 o1 = *reinterpret_cast<const float4*>(crow + 4);
                v[0] += o0.x; v[1] += o0.y; v[2] += o0.z; v[3] += o0.w;
                v[4] += o1.x; v[5] += o1.y; v[6] += o1.z; v[7] += o1.w;
            }
            if (STATS) {
#pragma unroll
                for (int j = 0; j < 8; j++) { csum[j] += v[j]; csq[j] += v[j] * v[j]; }
            }
            *reinterpret_cast<float4*>(crow)     = make_float4(v[0], v[1], v[2], v[3]);
            *reinterpret_cast<float4*>(crow + 4) = make_float4(v[4], v[5], v[6], v[7]);
        }
    }

    if (STATS) {
        __syncthreads();
#pragma unroll
        for (int j = 0; j < 8; j++) {
            atomicAdd(&s_sum[col_t * 8 + j], csum[j]);
            atomicAdd(&s_sq [col_t * 8 + j], csq[j]);
        }
        __syncthreads();
        if (tid < 128) {
            atomicAdd(&g_colsum[colBase + tid], s_sum[tid]);
            atomicAdd(&g_colsq [colBase + tid], s_sq [tid]);
        }
    }
}

// --------------------------- BatchNorm finalize/apply ------------------------
__global__ void bn_finalize(const float* __restrict__ gamma, const float* __restrict__ beta,
                            int n) {
    int c = threadIdx.x;
    if (c < H) {
        float inv  = 1.f / (float)n;
        float mean = g_colsum[c] * inv;
        float var  = g_colsq[c] * inv - mean * mean;
        float sc   = gamma[c] * rsqrtf(var + EPSV);
        g_scale[c] = sc;
        g_shift[c] = beta[c] - mean * sc;
    }
}
__global__ void bn_relu(int n) {
    int i  = blockIdx.x * blockDim.x + threadIdx.x;
    int n4 = n * (H / 4);
    if (i < n4) {
        int c4 = i & (H / 4 - 1);
        float4 v  = reinterpret_cast<float4*>(g_h)[i];
        float4 sc = reinterpret_cast<const float4*>(g_scale)[c4];
        float4 sh = reinterpret_cast<const float4*>(g_shift)[c4];
        v.x = fmaxf(fmaf(v.x, sc.x, sh.x), 0.f);
        v.y = fmaxf(fmaf(v.y, sc.y, sh.y), 0.f);
        v.z = fmaxf(fmaf(v.z, sc.z, sh.z), 0.f);
        v.w = fmaxf(fmaf(v.w, sc.w, sh.w), 0.f);
        reinterpret_cast<float4*>(g_h)[i] = v;
    }
}

// --------------------------- sparse segment ops ------------------------------
// One warp per incidence entry; rows of H=256 floats (2 float4 per lane).
__global__ void scatter_n2e(const int* __restrict__ node_idx,
                            const int* __restrict__ he_idx, int nnz) {
    int w    = (blockIdx.x * blockDim.x + threadIdx.x) >> 5;
    int lane = threadIdx.x & 31;
    if (w >= nnz) return;
    int s = __ldg(&node_idx[w]);
    int d = __ldg(&he_idx[w]);
    const float4* sp = reinterpret_cast<const float4*>(g_xw + (size_t)s * H);
    float* dp = g_he + (size_t)d * H;
#pragma unroll
    for (int q = 0; q < 2; q++) {
        float4 v = __ldg(sp + lane + q * 32);
        red_add_v4(dp + (size_t)(lane + q * 32) * 4, v);
    }
}
__global__ void scatter_e2n(const int* __restrict__ node_idx,
                            const int* __restrict__ he_idx, int nnz) {
    int w    = (blockIdx.x * blockDim.x + threadIdx.x) >> 5;
    int lane = threadIdx.x & 31;
    if (w >= nnz) return;
    int s = __ldg(&he_idx[w]);
    int d = __ldg(&node_idx[w]);
    const float4* sp = reinterpret_cast<const float4*>(g_he + (size_t)s * H);
    float* dp = g_agg + (size_t)d * H;
#pragma unroll
    for (int q = 0; q < 2; q++) {
        float4 v = __ldg(sp + lane + q * 32);
        red_add_v4(dp + (size_t)(lane + q * 32) * 4, v);
    }
}
__global__ void scale_he() {
    int i  = blockIdx.x * blockDim.x + threadIdx.x;
    int n4 = EMAX * (H / 4);
    if (i < n4) {
        int j   = i >> 6;
        int d   = g_Bdeg[j];
        float s = d > 0 ? 1.f / (float)d : 0.f;
        float4 v = reinterpret_cast<float4*>(g_he)[i];
        v.x *= s; v.y *= s; v.z *= s; v.w *= s;
        reinterpret_cast<float4*>(g_he)[i] = v;
    }
}
__global__ void conv_finish(const float* __restrict__ b, int n) {
    int i  = blockIdx.x * blockDim.x + threadIdx.x;
    int n4 = n * (H / 4);
    if (i < n4) {
        int v   = i >> 6;
        int c4  = i & 63;
        int d   = g_Ddeg[v];
        float s = d > 0 ? 1.f / (float)d : 0.f;
        float4 a  = reinterpret_cast<const float4*>(g_agg)[i];
        float4 bb = reinterpret_cast<const float4*>(b)[c4];
        a.x = fmaf(a.x, s, bb.x);
        a.y = fmaf(a.y, s, bb.y);
        a.z = fmaf(a.z, s, bb.z);
        a.w = fmaf(a.w, s, bb.w);
        reinterpret_cast<float4*>(g_h)[i] = a;
    }
}

// ------------------------------- pooling -------------------------------------
__global__ void pool_max(int n) {
    int i = blockIdx.x * blockDim.x + threadIdx.x;
    if (i < n * T) {
        int v = i >> 7;
        unsigned o = f2o(g_out[i]);
        atomicMax(&g_poolmx[(size_t)g_seg[v] * T + (i & (T - 1))], o);
    }
}
__global__ void pool_finalize(float* __restrict__ dout, int nseg) {
    int i = blockIdx.x * blockDim.x + threadIdx.x;
    if (i < nseg * T) {
        int s = i >> 7;
        dout[i] = (g_poolcnt[s] > 0) ? o2f(g_poolmx[i]) : 0.f;
    }
}

// ============================================================================
// Launch
// ============================================================================
extern "C" void kernel_launch(void* const* d_in, const int* in_sizes, int n_in,
                              void* d_out, int out_size)
{
    const float* x        = (const float*)d_in[0];
    const int*   node_idx = (const int*)  d_in[1];
    const int*   he_idx   = (const int*)  d_in[2];
    const int*   batch    = (const int*)  d_in[3];
    const int*   clusters = (const int*)  d_in[4];
    const float* W1  = (const float*)d_in[8];
    const float* b1  = (const float*)d_in[9];
    const float* g1  = (const float*)d_in[10];
    const float* be1 = (const float*)d_in[11];
    const float* lw0 = (const float*)d_in[12];
    const float* lb0 = (const float*)d_in[13];
    const float* cW1 = (const float*)d_in[14];
    const float* cb1 = (const float*)d_in[15];
    const float* lw1 = (const float*)d_in[16];
    const float* lb1 = (const float*)d_in[17];
    const float* cW2 = (const float*)d_in[18];
    const float* cb2 = (const float*)d_in[19];
    const float* lw2 = (const float*)d_in[20];
    const float* lb2 = (const float*)d_in[21];

    const int N    = in_sizes[3];
    const int NNZ  = in_sizes[1];
    const int F    = in_sizes[0] / N;   // 1024
    const int nseg = out_size / T;      // 1024
    const int C    = 64;

    float *p_h, *p_xw, *p_out;
    cudaGetSymbolAddress((void**)&p_h,   g_h);
    cudaGetSymbolAddress((void**)&p_xw,  g_xw);
    cudaGetSymbolAddress((void**)&p_out, g_out);

    const int GB  = (N + 127) / 128;
    const int n4  = N * (H / 4);
    const int he4 = EMAX * (H / 4);

    // ---- init + degrees + pooling metadata
    init_all<<<(n4 + 255) / 256, 256>>>(N);
    deg_hist<<<(NNZ + 255) / 256, 256>>>(node_idx, he_idx, NNZ);
    pool_prep<<<(N + 255) / 256, 256>>>(batch, clusters, N, C);

    // ---- layer 0: h_pre = x@W1 + b1 (BN stats in epilogue); then BN+ReLU
    gemm128<true, false><<<dim3(H / 128, GB), 256>>>(x, W1, b1, p_h, N, F, H);
    bn_finalize<<<1, H>>>(g1, be1, N);
    bn_relu<<<(n4 + 255) / 256, 256>>>(N);

    // out = h @ lw0 + lb0
    gemm128<false, false><<<dim3(T / 128, GB), 256>>>(p_h, lw0, lb0, p_out, N, H, T);

    // ---- two hypergraph conv layers
    for (int layer = 0; layer < 2; layer++) {
        const float* cW = layer ? cW2 : cW1;
        const float* cb = layer ? cb2 : cb1;
        const float* lw = layer ? lw2 : lw1;
        const float* lb = layer ? lb2 : lb1;

        gemm128<false, false><<<dim3(H / 128, GB), 256>>>(p_h, cW, nullptr, p_xw, N, H, H);

        if (layer) {   // g_he/g_agg pre-zeroed by init_all for layer 0
            zero_he<<<(he4 + 255) / 256, 256>>>();
            zero_agg<<<(n4 + 255) / 256, 256>>>(N);
        }
        scatter_n2e<<<(NNZ * 32 + 255) / 256, 256>>>(node_idx, he_idx, NNZ);
        scale_he<<<(he4 + 255) / 256, 256>>>();
        scatter_e2n<<<(NNZ * 32 + 255) / 256, 256>>>(node_idx, he_idx, NNZ);
        conv_finish<<<(n4 + 255) / 256, 256>>>(cb, N);

        gemm128<false, true><<<dim3(T / 128, GB), 256>>>(p_h, lw, lb, p_out, N, H, T);
    }

    // ---- pooling
    pool_max<<<(N * T + 255) / 256, 256>>>(N);
    pool_finalize<<<(nseg * T + 255) / 256, 256>>>((float*)d_out, nseg);
}

// round 4
// speedup vs baseline: 1.8679x; 1.8679x over previous
#include <cuda_runtime.h>
#include <cuda_bf16.h>
#include <cstdint>

// ============================================================================
// GNN_clusters_44057774522942
//   N=100000 nodes, F_in=1024, H=256, T=128, NNZ=400000, E=20000, B=16, C=64
// ============================================================================
constexpr int NMAX = 100000;
constexpr int EMAX = 20000;
constexpr int H    = 256;
constexpr int T    = 128;
constexpr int NSEG = 1024;   // B * C
constexpr float EPSV = 1e-5f;

// ------------------------- scratch (device globals) -------------------------
__device__ float g_h  [(size_t)NMAX * H];
__device__ float g_xw [(size_t)NMAX * H];
__device__ float g_agg[(size_t)NMAX * H];
__device__ float g_he [(size_t)EMAX * H];
__device__ float g_out[(size_t)NMAX * T];
__device__ float g_colsum[H];
__device__ float g_colsq [H];
__device__ float g_scale [H];
__device__ float g_shift [H];
__device__ int   g_Ddeg[NMAX];
__device__ int   g_Bdeg[EMAX];
__device__ int   g_seg [NMAX];
__device__ int   g_poolcnt[NSEG];
__device__ unsigned g_poolmx[NSEG * T];

// bf16 hi/lo split scratch (A operands: x [N,1024] or h [N,256])
__device__ __nv_bfloat16 g_Ahi[(size_t)NMAX * 1024];
__device__ __nv_bfloat16 g_Alo[(size_t)NMAX * 1024];
// weight splits, packed: W1 | lw0 | cW1 | lw1 | cW2 | lw2
constexpr int WOFF_W1  = 0;            // 1024*256
constexpr int WOFF_LW0 = 262144;       // 256*128
constexpr int WOFF_CW1 = 294912;       // 256*256
constexpr int WOFF_LW1 = 360448;       // 256*128
constexpr int WOFF_CW2 = 393216;       // 256*256
constexpr int WOFF_LW2 = 458752;       // 256*128
__device__ __nv_bfloat16 g_Whi[524288];
__device__ __nv_bfloat16 g_Wlo[524288];

// ------------------------------- tiny helpers -------------------------------
__device__ __forceinline__ unsigned f2o(float f) {
    unsigned u = __float_as_uint(f);
    return (u & 0x80000000u) ? ~u : (u | 0x80000000u);
}
__device__ __forceinline__ float o2f(unsigned o) {
    unsigned u = (o & 0x80000000u) ? (o ^ 0x80000000u) : ~o;
    return __uint_as_float(u);
}
__device__ __forceinline__ void red_add_v4(float* p, float4 v) {
    asm volatile("red.global.add.v4.f32 [%0], {%1,%2,%3,%4};"
                 :: "l"(p), "f"(v.x), "f"(v.y), "f"(v.z), "f"(v.w) : "memory");
}
__device__ __forceinline__ void cp16(uint32_t dst, const void* src, int sz) {
    asm volatile("cp.async.ca.shared.global [%0], [%1], 16, %2;"
                 :: "r"(dst), "l"(src), "r"(sz));
}
__device__ __forceinline__ void cp_commit() { asm volatile("cp.async.commit_group;"); }
template<int W> __device__ __forceinline__ void cp_wait() {
    asm volatile("cp.async.wait_group %0;" :: "n"(W));
}
__device__ __forceinline__ void ldsm4(uint32_t (&r)[4], uint32_t addr) {
    asm volatile("ldmatrix.sync.aligned.m8n8.x4.shared.b16 {%0,%1,%2,%3}, [%4];"
                 : "=r"(r[0]), "=r"(r[1]), "=r"(r[2]), "=r"(r[3]) : "r"(addr));
}
__device__ __forceinline__ void ldsm4t(uint32_t (&r)[4], uint32_t addr) {
    asm volatile("ldmatrix.sync.aligned.m8n8.x4.trans.shared.b16 {%0,%1,%2,%3}, [%4];"
                 : "=r"(r[0]), "=r"(r[1]), "=r"(r[2]), "=r"(r[3]) : "r"(addr));
}
__device__ __forceinline__ void mma16816(float* d, const uint32_t* a, uint32_t b0, uint32_t b1) {
    asm volatile("mma.sync.aligned.m16n8k16.row.col.f32.bf16.bf16.f32 "
                 "{%0,%1,%2,%3}, {%4,%5,%6,%7}, {%8,%9}, {%0,%1,%2,%3};"
                 : "+f"(d[0]), "+f"(d[1]), "+f"(d[2]), "+f"(d[3])
                 : "r"(a[0]), "r"(a[1]), "r"(a[2]), "r"(a[3]), "r"(b0), "r"(b1));
}
__device__ __forceinline__ void split2(float x, float y, uint32_t& hi, uint32_t& lo) {
    __nv_bfloat16 hx = __float2bfloat16(x), hy = __float2bfloat16(y);
    float rx = x - __bfloat162float(hx), ry = y - __bfloat162float(hy);
    __nv_bfloat162 h = __halves2bfloat162(hx, hy);
    __nv_bfloat162 l = __halves2bfloat162(__float2bfloat16(rx), __float2bfloat16(ry));
    hi = *reinterpret_cast<uint32_t*>(&h);
    lo = *reinterpret_cast<uint32_t*>(&l);
}

// ------------------------- fp32 -> bf16 hi/lo split --------------------------
__global__ void split8(const float4* __restrict__ src, uint4* __restrict__ hi,
                       uint4* __restrict__ lo, int n8) {
    int i = blockIdx.x * blockDim.x + threadIdx.x;
    if (i < n8) {
        float4 a = src[2 * i], b = src[2 * i + 1];
        uint4 h, l;
        split2(a.x, a.y, h.x, l.x); split2(a.z, a.w, h.y, l.y);
        split2(b.x, b.y, h.z, l.z); split2(b.z, b.w, h.w, l.w);
        hi[i] = h; lo[i] = l;
    }
}

// ------------------------------- init kernels --------------------------------
__global__ void init_all(int n) {
    int i = blockIdx.x * blockDim.x + threadIdx.x;
    int he4 = EMAX * (H / 4);
    int n4  = n * (H / 4);
    if (i < he4) reinterpret_cast<float4*>(g_he)[i]  = make_float4(0.f, 0.f, 0.f, 0.f);
    if (i < n4)  reinterpret_cast<float4*>(g_agg)[i] = make_float4(0.f, 0.f, 0.f, 0.f);
    if (i < n)    g_Ddeg[i] = 0;
    if (i < EMAX) g_Bdeg[i] = 0;
    if (i < NSEG * T) g_poolmx[i] = 0u;   // below f2o of any float
    if (i < NSEG) g_poolcnt[i] = 0;
    if (i < H) { g_colsum[i] = 0.f; g_colsq[i] = 0.f; }
}
__global__ void zero_agg(int n) {
    int i = blockIdx.x * blockDim.x + threadIdx.x;
    if (i < n * (H / 4)) reinterpret_cast<float4*>(g_agg)[i] = make_float4(0.f, 0.f, 0.f, 0.f);
}
__global__ void zero_he() {
    int i = blockIdx.x * blockDim.x + threadIdx.x;
    if (i < EMAX * (H / 4)) reinterpret_cast<float4*>(g_he)[i] = make_float4(0.f, 0.f, 0.f, 0.f);
}

// ----------------------------- degrees / pooling meta ------------------------
__global__ void deg_hist(const int* __restrict__ ni, const int* __restrict__ hi, int nnz) {
    int i = blockIdx.x * blockDim.x + threadIdx.x;
    if (i < nnz) { atomicAdd(&g_Ddeg[ni[i]], 1); atomicAdd(&g_Bdeg[hi[i]], 1); }
}
__global__ void pool_prep(const int* __restrict__ batch, const int* __restrict__ clus,
                          int n, int C) {
    int v = blockIdx.x * blockDim.x + threadIdx.x;
    if (v < n) {
        int s = batch[v] * C + clus[v];
        g_seg[v] = s;
        atomicAdd(&g_poolcnt[s], 1);
    }
}

// ============================================================================
// bf16x3 split GEMM on tensor cores.
// C[N,M] = (Ahi+Alo)[N,K] @ (Bhi+Blo)[K,M] (+bias) (+=C if ACCUM), fp32 accum.
// Block tile 128x128, BK=32, 256 threads (8 warps, 4x2), warp tile 32x64.
// cp.async double-buffered; padded smem (A stride 40, B stride 136 bf16)
// for conflict-free ldmatrix. Requires K%32==0, M%128==0.
// ============================================================================
constexpr int LDA_S = 40;
constexpr int LDB_S = 136;
constexpr int SOFF_ALO = 128 * LDA_S * 2;          // 10240
constexpr int SOFF_BHI = 2 * SOFF_ALO;             // 20480
constexpr int SOFF_BLO = SOFF_BHI + 32 * LDB_S * 2;// 29184
constexpr int STAGE_B  = SOFF_BLO + 32 * LDB_S * 2;// 37888
constexpr int GEMM_SMEM = 2 * STAGE_B;             // 75776

template<bool ACCUM>
__global__ void __launch_bounds__(256)
gemm_bf16(const __nv_bfloat16* __restrict__ Ahi, const __nv_bfloat16* __restrict__ Alo,
          const __nv_bfloat16* __restrict__ Bhi, const __nv_bfloat16* __restrict__ Blo,
          const float* __restrict__ bias, float* __restrict__ C,
          int N, int K, int M)
{
    extern __shared__ char smem[];
    const uint32_t sbase = (uint32_t)__cvta_generic_to_shared(smem);
    const int tid = threadIdx.x, lane = tid & 31, wid = tid >> 5;
    const int warp_m = wid & 3, warp_n = wid >> 2;
    const int rowBase = blockIdx.y * 128, colBase = blockIdx.x * 128;

    float acc[2][8][4];
#pragma unroll
    for (int mt = 0; mt < 2; mt++)
#pragma unroll
        for (int nt = 0; nt < 8; nt++)
#pragma unroll
            for (int q = 0; q < 4; q++) acc[mt][nt][q] = 0.f;

    auto load_stage = [&](int s, int k0) {
        uint32_t aH = sbase + s * STAGE_B, aL = aH + SOFF_ALO;
        uint32_t bH = aH + SOFF_BHI,       bL = aH + SOFF_BLO;
#pragma unroll
        for (int it = 0; it < 2; it++) {          // A: 512 chunks of 16B (hi)+(lo)
            int chunk = tid + it * 256;
            int r = chunk >> 2, seg = chunk & 3;
            int gr = min(rowBase + r, N - 1);
            int sz = (rowBase + r) < N ? 16 : 0;
            size_t go = (size_t)gr * K + k0 + seg * 8;
            uint32_t so = (uint32_t)(r * LDA_S + seg * 8) * 2;
            cp16(aH + so, Ahi + go, sz);
            cp16(aL + so, Alo + go, sz);
        }
#pragma unroll
        for (int it = 0; it < 2; it++) {          // B
            int chunk = tid + it * 256;
            int r = chunk >> 4, seg = chunk & 15;
            size_t go = (size_t)(k0 + r) * M + colBase + seg * 8;
            uint32_t so = (uint32_t)(r * LDB_S + seg * 8) * 2;
            cp16(bH + so, Bhi + go, 16);
            cp16(bL + so, Blo + go, 16);
        }
    };

    auto compute = [&](int s) {
        uint32_t aH = sbase + s * STAGE_B, aL = aH + SOFF_ALO;
        uint32_t bH = aH + SOFF_BHI,       bL = aH + SOFF_BLO;
#pragma unroll
        for (int ks = 0; ks < 2; ks++) {
            const int kofs = ks * 16;
            uint32_t ah[2][4], al[2][4], bh[4][4], bl[4][4];
#pragma unroll
            for (int mt = 0; mt < 2; mt++) {
                uint32_t off = (uint32_t)((warp_m * 32 + mt * 16 + (lane & 15)) * LDA_S
                                          + kofs + ((lane >> 4) << 3)) * 2;
                ldsm4(ah[mt], aH + off);
                ldsm4(al[mt], aL + off);
            }
#pragma unroll
            for (int nt2 = 0; nt2 < 4; nt2++) {
                uint32_t off = (uint32_t)((kofs + (lane & 15)) * LDB_S
                                          + warp_n * 64 + nt2 * 16 + ((lane >> 4) << 3)) * 2;
                ldsm4t(bh[nt2], bH + off);
                ldsm4t(bl[nt2], bL + off);
            }
#pragma unroll
            for (int mt = 0; mt < 2; mt++)
#pragma unroll
                for (int nt = 0; nt < 8; nt++) {
                    int p = nt >> 1, hh = (nt & 1) * 2;
                    mma16816(acc[mt][nt], ah[mt], bh[p][hh], bh[p][hh + 1]);  // hi*hi
                    mma16816(acc[mt][nt], al[mt], bh[p][hh], bh[p][hh + 1]);  // lo*hi
                    mma16816(acc[mt][nt], ah[mt], bl[p][hh], bl[p][hh + 1]);  // hi*lo
                }
        }
    };

    load_stage(0, 0);
    cp_commit();
    const int nk = K >> 5;
    for (int k = 0; k < nk; k++) {
        if (k + 1 < nk) { load_stage((k + 1) & 1, (k + 1) << 5); cp_commit(); cp_wait<1>(); }
        else            { cp_wait<0>(); }
        __syncthreads();
        compute(k & 1);
        __syncthreads();
    }

    // epilogue
    const int gid = lane >> 2, tig = lane & 3;
#pragma unroll
    for (int nt = 0; nt < 8; nt++) {
        int col = colBase + warp_n * 64 + nt * 8 + tig * 2;
        float b0 = bias ? bias[col]     : 0.f;
        float b1 = bias ? bias[col + 1] : 0.f;
#pragma unroll
        for (int mt = 0; mt < 2; mt++) {
            int r0 = rowBase + warp_m * 32 + mt * 16 + gid;
#pragma unroll
            for (int hh = 0; hh < 2; hh++) {
                int r = r0 + hh * 8;
                if (r < N) {
                    float2* p = reinterpret_cast<float2*>(C + (size_t)r * M + col);
                    float2 v = make_float2(acc[mt][nt][hh * 2] + b0,
                                           acc[mt][nt][hh * 2 + 1] + b1);
                    if (ACCUM) { float2 o = *p; v.x += o.x; v.y += o.y; }
                    *p = v;
                }
            }
        }
    }
}

// --------------------------- BatchNorm ---------------------------------------
__global__ void bn_stats(int n) {   // column sums over g_h [n, H]
    int c = threadIdx.x;            // 256 threads = H cols
    int r0 = blockIdx.x * 128;
    int r1 = min(r0 + 128, n);
    float s = 0.f, q = 0.f;
    for (int r = r0; r < r1; r++) {
        float v = g_h[(size_t)r * H + c];
        s += v; q += v * v;
    }
    atomicAdd(&g_colsum[c], s);
    atomicAdd(&g_colsq[c], q);
}
__global__ void bn_finalize(const float* __restrict__ gamma, const float* __restrict__ beta,
                            int n) {
    int c = threadIdx.x;
    if (c < H) {
        float inv  = 1.f / (float)n;
        float mean = g_colsum[c] * inv;
        float var  = g_colsq[c] * inv - mean * mean;
        float sc   = gamma[c] * rsqrtf(var + EPSV);
        g_scale[c] = sc;
        g_shift[c] = beta[c] - mean * sc;
    }
}
__global__ void bn_relu(int n) {
    int i  = blockIdx.x * blockDim.x + threadIdx.x;
    int n4 = n * (H / 4);
    if (i < n4) {
        int c4 = i & (H / 4 - 1);
        float4 v  = reinterpret_cast<float4*>(g_h)[i];
        float4 sc = reinterpret_cast<const float4*>(g_scale)[c4];
        float4 sh = reinterpret_cast<const float4*>(g_shift)[c4];
        v.x = fmaxf(fmaf(v.x, sc.x, sh.x), 0.f);
        v.y = fmaxf(fmaf(v.y, sc.y, sh.y), 0.f);
        v.z = fmaxf(fmaf(v.z, sc.z, sh.z), 0.f);
        v.w = fmaxf(fmaf(v.w, sc.w, sh.w), 0.f);
        reinterpret_cast<float4*>(g_h)[i] = v;
    }
}

// --------------------------- sparse segment ops ------------------------------
__global__ void scatter_n2e(const int* __restrict__ node_idx,
                            const int* __restrict__ he_idx, int nnz) {
    int w    = (blockIdx.x * blockDim.x + threadIdx.x) >> 5;
    int lane = threadIdx.x & 31;
    if (w >= nnz) return;
    int s = __ldg(&node_idx[w]);
    int d = __ldg(&he_idx[w]);
    const float4* sp = reinterpret_cast<const float4*>(g_xw + (size_t)s * H);
    float* dp = g_he + (size_t)d * H;
#pragma unroll
    for (int q = 0; q < 2; q++) {
        float4 v = __ldg(sp + lane + q * 32);
        red_add_v4(dp + (size_t)(lane + q * 32) * 4, v);
    }
}
__global__ void scatter_e2n(const int* __restrict__ node_idx,
                            const int* __restrict__ he_idx, int nnz) {
    int w    = (blockIdx.x * blockDim.x + threadIdx.x) >> 5;
    int lane = threadIdx.x & 31;
    if (w >= nnz) return;
    int s = __ldg(&he_idx[w]);
    int d = __ldg(&node_idx[w]);
    const float4* sp = reinterpret_cast<const float4*>(g_he + (size_t)s * H);
    float* dp = g_agg + (size_t)d * H;
#pragma unroll
    for (int q = 0; q < 2; q++) {
        float4 v = __ldg(sp + lane + q * 32);
        red_add_v4(dp + (size_t)(lane + q * 32) * 4, v);
    }
}
__global__ void scale_he() {
    int i  = blockIdx.x * blockDim.x + threadIdx.x;
    if (i < EMAX * (H / 4)) {
        int j   = i >> 6;
        int d   = g_Bdeg[j];
        float s = d > 0 ? 1.f / (float)d : 0.f;
        float4 v = reinterpret_cast<float4*>(g_he)[i];
        v.x *= s; v.y *= s; v.z *= s; v.w *= s;
        reinterpret_cast<float4*>(g_he)[i] = v;
    }
}
__global__ void conv_finish(const float* __restrict__ b, int n) {
    int i  = blockIdx.x * blockDim.x + threadIdx.x;
    if (i < n * (H / 4)) {
        int v   = i >> 6;
        int c4  = i & 63;
        int d   = g_Ddeg[v];
        float s = d > 0 ? 1.f / (float)d : 0.f;
        float4 a  = reinterpret_cast<const float4*>(g_agg)[i];
        float4 bb = reinterpret_cast<const float4*>(b)[c4];
        a.x = fmaf(a.x, s, bb.x);
        a.y = fmaf(a.y, s, bb.y);
        a.z = fmaf(a.z, s, bb.z);
        a.w = fmaf(a.w, s, bb.w);
        reinterpret_cast<float4*>(g_h)[i] = a;
    }
}

// ------------------------------- pooling -------------------------------------
__global__ void pool_max(int n) {
    int i = blockIdx.x * blockDim.x + threadIdx.x;
    if (i < n * T) {
        int v = i >> 7;
        unsigned o = f2o(g_out[i]);
        atomicMax(&g_poolmx[(size_t)g_seg[v] * T + (i & (T - 1))], o);
    }
}
__global__ void pool_finalize(float* __restrict__ dout, int nseg) {
    int i = blockIdx.x * blockDim.x + threadIdx.x;
    if (i < nseg * T) {
        int s = i >> 7;
        dout[i] = (g_poolcnt[s] > 0) ? o2f(g_poolmx[i]) : 0.f;
    }
}

// ============================================================================
// Launch
// ============================================================================
extern "C" void kernel_launch(void* const* d_in, const int* in_sizes, int n_in,
                              void* d_out, int out_size)
{
    const float* x        = (const float*)d_in[0];
    const int*   node_idx = (const int*)  d_in[1];
    const int*   he_idx   = (const int*)  d_in[2];
    const int*   batch    = (const int*)  d_in[3];
    const int*   clusters = (const int*)  d_in[4];
    const float* W1  = (const float*)d_in[8];
    const float* b1  = (const float*)d_in[9];
    const float* g1  = (const float*)d_in[10];
    const float* be1 = (const float*)d_in[11];
    const float* lw0 = (const float*)d_in[12];
    const float* lb0 = (const float*)d_in[13];
    const float* cb1 = (const float*)d_in[15];
    const float* lb1 = (const float*)d_in[17];
    const float* cb2 = (const float*)d_in[19];
    const float* lb2 = (const float*)d_in[21];
    const float* cW1 = (const float*)d_in[14];
    const float* lw1 = (const float*)d_in[16];
    const float* cW2 = (const float*)d_in[18];
    const float* lw2 = (const float*)d_in[20];

    const int N    = in_sizes[3];
    const int NNZ  = in_sizes[1];
    const int F    = in_sizes[0] / N;   // 1024
    const int nseg = out_size / T;      // 1024
    const int C    = 64;

    float *p_h, *p_xw, *p_out;
    __nv_bfloat16 *p_Ahi, *p_Alo, *p_Whi, *p_Wlo;
    cudaGetSymbolAddress((void**)&p_h,   g_h);
    cudaGetSymbolAddress((void**)&p_xw,  g_xw);
    cudaGetSymbolAddress((void**)&p_out, g_out);
    cudaGetSymbolAddress((void**)&p_Ahi, g_Ahi);
    cudaGetSymbolAddress((void**)&p_Alo, g_Alo);
    cudaGetSymbolAddress((void**)&p_Whi, g_Whi);
    cudaGetSymbolAddress((void**)&p_Wlo, g_Wlo);

    cudaFuncSetAttribute(gemm_bf16<false>, cudaFuncAttributeMaxDynamicSharedMemorySize, GEMM_SMEM);
    cudaFuncSetAttribute(gemm_bf16<true>,  cudaFuncAttributeMaxDynamicSharedMemorySize, GEMM_SMEM);

    const int GB  = (N + 127) / 128;
    const int n4  = N * (H / 4);
    const int he4 = EMAX * (H / 4);
    const int hsplit8 = N * H / 8;

    auto splitW = [&](const float* src, int off, int elems) {
        split8<<<(elems / 8 + 255) / 256, 256>>>((const float4*)src,
                                                 (uint4*)(p_Whi + off), (uint4*)(p_Wlo + off),
                                                 elems / 8);
    };

    // ---- init + degrees + pooling metadata + weight splits
    init_all<<<(n4 + 255) / 256, 256>>>(N);
    deg_hist<<<(NNZ + 255) / 256, 256>>>(node_idx, he_idx, NNZ);
    pool_prep<<<(N + 255) / 256, 256>>>(batch, clusters, N, C);
    splitW(W1,  WOFF_W1,  1024 * 256);
    splitW(lw0, WOFF_LW0, 256 * 128);
    splitW(cW1, WOFF_CW1, 256 * 256);
    splitW(lw1, WOFF_LW1, 256 * 128);
    splitW(cW2, WOFF_CW2, 256 * 256);
    splitW(lw2, WOFF_LW2, 256 * 128);

    // ---- layer 0: h = x @ W1 + b1 ; BN(batch stats) ; ReLU
    split8<<<(N * F / 8 + 255) / 256, 256>>>((const float4*)x, (uint4*)p_Ahi, (uint4*)p_Alo, N * F / 8);
    gemm_bf16<false><<<dim3(H / 128, GB), 256, GEMM_SMEM>>>(
        p_Ahi, p_Alo, p_Whi + WOFF_W1, p_Wlo + WOFF_W1, b1, p_h, N, F, H);
    bn_stats<<<GB, 256>>>(N);
    bn_finalize<<<1, H>>>(g1, be1, N);
    bn_relu<<<(n4 + 255) / 256, 256>>>(N);

    // ---- h0 split ; out = h0 @ lw0 + lb0 ; xw = h0 @ cW1
    split8<<<(hsplit8 + 255) / 256, 256>>>((const float4*)p_h, (uint4*)p_Ahi, (uint4*)p_Alo, hsplit8);
    gemm_bf16<false><<<dim3(T / 128, GB), 256, GEMM_SMEM>>>(
        p_Ahi, p_Alo, p_Whi + WOFF_LW0, p_Wlo + WOFF_LW0, lb0, p_out, N, H, T);

    for (int layer = 0; layer < 2; layer++) {
        const int woff_c = layer ? WOFF_CW2 : WOFF_CW1;
        const int woff_l = layer ? WOFF_LW2 : WOFF_LW1;
        const float* cb = layer ? cb2 : cb1;
        const float* lb = layer ? lb2 : lb1;

        // xw = h @ cW  (uses current h split, already in g_Ahi/g_Alo)
        gemm_bf16<false><<<dim3(H / 128, GB), 256, GEMM_SMEM>>>(
            p_Ahi, p_Alo, p_Whi + woff_c, p_Wlo + woff_c, nullptr, p_xw, N, H, H);

        if (layer) {
            zero_he<<<(he4 + 255) / 256, 256>>>();
            zero_agg<<<(n4 + 255) / 256, 256>>>(N);
        }
        scatter_n2e<<<(NNZ * 32 + 255) / 256, 256>>>(node_idx, he_idx, NNZ);
        scale_he<<<(he4 + 255) / 256, 256>>>();
        scatter_e2n<<<(NNZ * 32 + 255) / 256, 256>>>(node_idx, he_idx, NNZ);
        conv_finish<<<(n4 + 255) / 256, 256>>>(cb, N);

        // split new h ; out += h @ lw + lb
        split8<<<(hsplit8 + 255) / 256, 256>>>((const float4*)p_h, (uint4*)p_Ahi, (uint4*)p_Alo, hsplit8);
        gemm_bf16<true><<<dim3(T / 128, GB), 256, GEMM_SMEM>>>(
            p_Ahi, p_Alo, p_Whi + woff_l, p_Wlo + woff_l, lb, p_out, N, H, T);
    }

    // ---- pooling
    pool_max<<<(N * T + 255) / 256, 256>>>(N);
    pool_finalize<<<(nseg * T + 255) / 256, 256>>>((float*)d_out, nseg);
}